// round 1
// baseline (speedup 1.0000x reference)
#include <cuda_runtime.h>
#include <math.h>

#define B 64
#define T 2048
#define H 512
#define S 512
#define K 128
#define V 128
#define NS 8
#define CHUNK (T/NS)        // 256 rows of T per CTA
#define TILE 16             // rows per smem tile
#define NTILES (CHUNK/TILE) // 16

// ---- scratch (no allocations allowed) ----
__device__ float g_w[B*H];        // folded query-key weight per batch
__device__ float g_c[B];          // q·bh
__device__ float g_e[B*T];        // energies
__device__ float g_pm[B*NS];      // partial max
__device__ float g_pz[B*NS];      // partial unmasked Z
__device__ float g_ps[B*NS];      // partial masked S
__device__ float g_pu[B*NS*H];    // partial weighted sums
__device__ float g_m[B];          // final max
__device__ float g_coef[B];       // 1/(Z*denom)

// ---------------- Kernel A: per-batch prep (q -> w, c) ----------------
__global__ void prep_kernel(const float* __restrict__ state,
                            const float* __restrict__ Ws, const float* __restrict__ bs,
                            const float* __restrict__ Wh, const float* __restrict__ bh) {
    const int b = blockIdx.x, tid = threadIdx.x;   // 256 threads
    __shared__ float st[S];
    __shared__ float q[K];
    st[tid]       = state[b*S + tid];
    st[tid + 256] = state[b*S + tid + 256];
    __syncthreads();
    if (tid < K) {
        const float4* wr  = (const float4*)(Ws + (size_t)tid*S);
        const float4* stv = (const float4*)st;
        float acc = 0.f;
        #pragma unroll 8
        for (int i = 0; i < S/4; i++) {
            float4 a = wr[i], x = stv[i];
            acc += a.x*x.x + a.y*x.y + a.z*x.z + a.w*x.w;
        }
        q[tid] = acc + bs[tid];
    }
    __syncthreads();
    for (int h = tid; h < H; h += 256) {
        float acc = 0.f;
        #pragma unroll 8
        for (int k = 0; k < K; k++) acc += Wh[k*H + h] * q[k];
        g_w[b*H + h] = acc;
    }
    if (tid == 0) {
        float c = 0.f;
        #pragma unroll 8
        for (int k = 0; k < K; k++) c += q[k]*bh[k];
        g_c[b] = c;
    }
}

// ---------------- Kernel B: flash pass over listener_output ----------------
// grid (NS, B), 256 threads. One streaming read of x; online softmax over the
// full (unmasked) chunk + masked weighted accumulation of x rows.
__global__ void flash_kernel(const float* __restrict__ x,
                             const int* __restrict__ lens) {
    const int split = blockIdx.x, b = blockIdx.y;
    const int tid = threadIdx.x;
    const int warp = tid >> 5, lane = tid & 31;

    __shared__ float tile[TILE][H];  // 32 KB
    __shared__ float wsm[H];         // 2 KB
    __shared__ float esm[TILE];
    __shared__ float psm[TILE];
    __shared__ float pmsm[TILE];

    wsm[tid]       = g_w[b*H + tid];
    wsm[tid + 256] = g_w[b*H + tid + 256];
    const float cb = g_c[b];
    int len = lens[b];
    if (b == 0) len = T;
    if (len > T) len = T;

    float m = -INFINITY, Z = 0.f, Ssum = 0.f;
    float u0 = 0.f, u1 = 0.f;

    const int t0chunk = split * CHUNK;
    const float* xb = x + (size_t)b * T * H;

    for (int ti = 0; ti < NTILES; ti++) {
        const int trow = t0chunk + ti * TILE;
        __syncthreads();  // protect previous tile/esm/psm reuse
        // stage contiguous TILE*H block
        {
            const float4* src = (const float4*)(xb + (size_t)trow * H);
            float4* dst = (float4*)(&tile[0][0]);
            #pragma unroll
            for (int i = 0; i < (TILE*H/4)/256; i++)
                dst[tid + i*256] = src[tid + i*256];
        }
        __syncthreads();
        // energies: 8 warps x 2 rows each
        #pragma unroll
        for (int j = 0; j < TILE/8; j++) {
            const int r = warp * (TILE/8) + j;
            float acc = 0.f;
            #pragma unroll
            for (int i = 0; i < H/32; i++)
                acc += tile[r][lane + i*32] * wsm[lane + i*32];
            #pragma unroll
            for (int o = 16; o > 0; o >>= 1)
                acc += __shfl_xor_sync(0xffffffffu, acc, o);
            if (lane == 0) {
                const float e = acc + cb;
                esm[r] = e;
                g_e[b*T + trow + r] = e;
            }
        }
        __syncthreads();
        // online softmax update (replicated per-thread; identical values)
        float tmax = esm[0];
        #pragma unroll
        for (int r = 1; r < TILE; r++) tmax = fmaxf(tmax, esm[r]);
        const float m_new = fmaxf(m, tmax);
        const float scale = __expf(m - m_new);
        u0 *= scale; u1 *= scale; Z *= scale; Ssum *= scale;
        m = m_new;
        if (tid < TILE) {
            const float p = __expf(esm[tid] - m_new);
            psm[tid]  = p;
            pmsm[tid] = (trow + tid < len) ? p : 0.f;
        }
        __syncthreads();
        #pragma unroll
        for (int r = 0; r < TILE; r++) Z += psm[r];
        if (trow < len) {  // mask is a prefix; skip fully-invalid tiles
            #pragma unroll
            for (int r = 0; r < TILE; r++) {
                const float p = pmsm[r];
                Ssum += p;
                u0 += p * tile[r][tid];
                u1 += p * tile[r][tid + 256];
            }
        }
    }
    const int pi = b*NS + split;
    g_pu[pi*H + tid]       = u0;
    g_pu[pi*H + tid + 256] = u1;
    if (tid == 0) { g_pm[pi] = m; g_pz[pi] = Z; g_ps[pi] = Ssum; }
}

// ---------------- Kernel C: combine partials + context GEMV ----------------
__global__ void combine_kernel(const float* __restrict__ Wv, const float* __restrict__ bv,
                               float* __restrict__ out) {
    const int b = blockIdx.x, tid = threadIdx.x;  // 128 threads
    __shared__ float U[H];
    float m = -INFINITY;
    #pragma unroll
    for (int i = 0; i < NS; i++) m = fmaxf(m, g_pm[b*NS + i]);
    float Z = 0.f, Ssum = 0.f;
    #pragma unroll
    for (int i = 0; i < NS; i++) {
        const float f = __expf(g_pm[b*NS + i] - m);
        Z    += g_pz[b*NS + i] * f;
        Ssum += g_ps[b*NS + i] * f;
    }
    for (int h = tid; h < H; h += 128) {
        float acc = 0.f;
        #pragma unroll
        for (int i = 0; i < NS; i++)
            acc += g_pu[(b*NS + i)*H + h] * __expf(g_pm[b*NS + i] - m);
        U[h] = acc;
    }
    __syncthreads();
    const float Snorm = Ssum / Z;
    const float denom = fmaxf(Snorm, 1e-12f);
    const float coef  = 1.f / (Z * denom);   // attn_t = exp(e-m)*coef (valid t)
    {
        const int v = tid;
        const float4* wr = (const float4*)(Wv + (size_t)v*H);
        const float4* Uv = (const float4*)U;
        float acc = 0.f;
        #pragma unroll 8
        for (int i = 0; i < H/4; i++) {
            float4 a = wr[i], xx = Uv[i];
            acc += a.x*xx.x + a.y*xx.y + a.z*xx.z + a.w*xx.w;
        }
        out[b*V + v] = acc * coef + bv[v] * (Ssum * coef);
    }
    if (tid == 0) { g_m[b] = m; g_coef[b] = coef; }
}

// ---------------- Kernel D: write attention output ----------------
__global__ void attn_out_kernel(const int* __restrict__ lens, float* __restrict__ out) {
    const int idx = blockIdx.x * 256 + threadIdx.x;  // < B*T
    const int b = idx >> 11;        // T = 2048
    const int t = idx & (T - 1);
    int len = lens[b];
    if (b == 0) len = T;
    if (len > T) len = T;
    float v = 0.f;
    if (t < len) v = __expf(g_e[idx] - g_m[b]) * g_coef[b];
    out[B*V + idx] = v;
}

extern "C" void kernel_launch(void* const* d_in, const int* in_sizes, int n_in,
                              void* d_out, int out_size) {
    const float* state = (const float*)d_in[0];
    const float* x     = (const float*)d_in[1];  // listener_output (B,T,H)
    const int*   lens  = (const int*)  d_in[2];
    const float* Ws    = (const float*)d_in[3];
    const float* bs    = (const float*)d_in[4];
    const float* Wh    = (const float*)d_in[5];
    const float* bh    = (const float*)d_in[6];
    const float* Wv    = (const float*)d_in[7];
    const float* bv    = (const float*)d_in[8];
    float* out = (float*)d_out;

    prep_kernel<<<B, 256>>>(state, Ws, bs, Wh, bh);
    dim3 grid(NS, B);
    flash_kernel<<<grid, 256>>>(x, lens);
    combine_kernel<<<B, 128>>>(Wv, bv, out);
    attn_out_kernel<<<(B*T)/256, 256>>>(lens, out);
}

// round 2
// speedup vs baseline: 1.4086x; 1.4086x over previous
#include <cuda_runtime.h>
#include <math.h>

#define B 64
#define T 2048
#define H 512
#define S 512
#define K 128
#define V 128
#define NS 16
#define CHUNK (T/NS)        // 128 rows per CTA
#define TILE 8              // rows per smem tile
#define MAXTILES (CHUNK/TILE)

// ---- scratch (no allocations allowed) ----
__device__ float g_w[B*H];        // folded query-key weight per batch
__device__ float g_c[B];          // q . bh
__device__ float g_e[B*T];        // energies (valid t only)
__device__ float g_pm[B*NS];      // partial max
__device__ float g_ps[B*NS];      // partial masked sum S
__device__ float g_pu[B*NS*H];    // partial weighted sums
__device__ float g_m[B];          // final max
__device__ float g_coef[B];       // 1/S

__device__ __forceinline__ void cp16(float* smem, const float* gmem) {
    unsigned s = (unsigned)__cvta_generic_to_shared(smem);
    asm volatile("cp.async.cg.shared.global [%0], [%1], 16;" :: "r"(s), "l"(gmem));
}
__device__ __forceinline__ void cp_commit() {
    asm volatile("cp.async.commit_group;");
}

// ---------------- Kernel A: per-batch prep (q -> w, c) ----------------
__global__ void prep_kernel(const float* __restrict__ state,
                            const float* __restrict__ Ws, const float* __restrict__ bs,
                            const float* __restrict__ Wh, const float* __restrict__ bh) {
    const int b = blockIdx.x, tid = threadIdx.x;   // 256 threads
    __shared__ float st[S];
    __shared__ float q[K];
    st[tid]       = state[b*S + tid];
    st[tid + 256] = state[b*S + tid + 256];
    __syncthreads();
    if (tid < K) {
        const float4* wr  = (const float4*)(Ws + (size_t)tid*S);
        const float4* stv = (const float4*)st;
        float acc = 0.f;
        #pragma unroll 8
        for (int i = 0; i < S/4; i++) {
            float4 a = wr[i], x = stv[i];
            acc += a.x*x.x + a.y*x.y + a.z*x.z + a.w*x.w;
        }
        q[tid] = acc + bs[tid];
    }
    __syncthreads();
    for (int h = tid; h < H; h += 256) {
        float acc = 0.f;
        #pragma unroll 8
        for (int k = 0; k < K; k++) acc += Wh[k*H + h] * q[k];
        g_w[b*H + h] = acc;
    }
    if (tid == 0) {
        float c = 0.f;
        #pragma unroll 8
        for (int k = 0; k < K; k++) c += q[k]*bh[k];
        g_c[b] = c;
    }
}

// ---------------- Kernel B: flash pass (valid rows only) ----------------
// grid (NS, B), 256 threads. cp.async double-buffered tiles. Masked-out rows
// are never read: outside the eps-corner the unmasked Z cancels exactly.
__global__ void __launch_bounds__(256) flash_kernel(const float* __restrict__ x,
                                                    const int* __restrict__ lens) {
    const int split = blockIdx.x, b = blockIdx.y;
    const int tid = threadIdx.x;
    const int warp = tid >> 5, lane = tid & 31;

    __shared__ float tile[2][TILE*H];  // 2 x 16 KB
    __shared__ float wsm[H];           // 2 KB
    __shared__ float esm[TILE];
    __shared__ float psm[TILE];

    int len = lens[b];
    if (b == 0) len = T;
    if (len > T) len = T;
    const int t0 = split * CHUNK;
    int rows = len - t0;
    if (rows > CHUNK) rows = CHUNK;
    const int pi = b*NS + split;
    if (rows <= 0) {
        if (tid == 0) { g_pm[pi] = -INFINITY; g_ps[pi] = 0.f; }
        ((float2*)(g_pu + (size_t)pi*H))[tid] = make_float2(0.f, 0.f);
        return;
    }
    const int ntiles = (rows + TILE - 1) / TILE;

    const float* xb = x + (size_t)b*T*H + (size_t)t0*H;

    // prefetch tile 0
    {
        float* dst = tile[0];
        const float* src = xb;
        #pragma unroll
        for (int i = 0; i < (TILE*H/4)/256; i++)
            cp16(dst + (tid + i*256)*4, src + (tid + i*256)*4);
        cp_commit();
    }

    wsm[tid]       = g_w[b*H + tid];
    wsm[tid + 256] = g_w[b*H + tid + 256];
    const float cb = g_c[b];

    float m = -INFINITY, Ssum = 0.f;
    float2 u = make_float2(0.f, 0.f);

    for (int ti = 0; ti < ntiles; ti++) {
        if (ti + 1 < ntiles) {
            float* dst = tile[(ti+1) & 1];
            const float* src = xb + (size_t)(ti+1)*TILE*H;
            #pragma unroll
            for (int i = 0; i < (TILE*H/4)/256; i++)
                cp16(dst + (tid + i*256)*4, src + (tid + i*256)*4);
            cp_commit();
            asm volatile("cp.async.wait_group 1;");
        } else {
            asm volatile("cp.async.wait_group 0;");
        }
        __syncthreads();

        float* tl = tile[ti & 1];
        // energy: one warp per row
        {
            const int r = warp;
            const float4* row = (const float4*)(tl + r*H);
            const float4* wv  = (const float4*)wsm;
            float acc = 0.f;
            #pragma unroll
            for (int i = 0; i < H/128; i++) {
                float4 a = row[lane + i*32], w = wv[lane + i*32];
                acc += a.x*w.x + a.y*w.y + a.z*w.z + a.w*w.w;
            }
            #pragma unroll
            for (int o = 16; o > 0; o >>= 1)
                acc += __shfl_xor_sync(0xffffffffu, acc, o);
            if (lane == 0) {
                const int t = t0 + ti*TILE + r;
                const float e = acc + cb;
                if (t < len) { esm[r] = e; g_e[b*T + t] = e; }
                else         { esm[r] = -INFINITY; }
            }
        }
        __syncthreads();
        // online softmax update (replicated, identical across threads)
        float tmax = esm[0];
        #pragma unroll
        for (int r = 1; r < TILE; r++) tmax = fmaxf(tmax, esm[r]);
        const float m_new = fmaxf(m, tmax);
        const float scale = __expf(m - m_new);
        u.x *= scale; u.y *= scale; Ssum *= scale;
        m = m_new;
        if (tid < TILE) psm[tid] = __expf(esm[tid] - m_new);  // exp(-inf)=0
        __syncthreads();
        #pragma unroll
        for (int r = 0; r < TILE; r++) {
            const float p = psm[r];
            Ssum += p;
            const float2 v = ((const float2*)(tl + r*H))[tid];
            u.x += p * v.x;
            u.y += p * v.y;
        }
        __syncthreads();  // buffer (ti&1) free for prefetch at ti+1
    }

    ((float2*)(g_pu + (size_t)pi*H))[tid] = u;
    if (tid == 0) { g_pm[pi] = m; g_ps[pi] = Ssum; }
}

// ---------------- Kernel C: combine partials + context GEMV ----------------
__global__ void combine_kernel(const float* __restrict__ Wv, const float* __restrict__ bv,
                               float* __restrict__ out) {
    const int b = blockIdx.x, tid = threadIdx.x;  // 128 threads
    __shared__ float U[H];
    __shared__ float fac[NS];
    float m = -INFINITY;
    #pragma unroll
    for (int i = 0; i < NS; i++) m = fmaxf(m, g_pm[b*NS + i]);
    if (tid < NS) fac[tid] = __expf(g_pm[b*NS + tid] - m);
    __syncthreads();
    float Ssum = 0.f;
    #pragma unroll
    for (int i = 0; i < NS; i++) Ssum += g_ps[b*NS + i] * fac[i];
    for (int h = tid; h < H; h += 128) {
        float acc = 0.f;
        #pragma unroll
        for (int i = 0; i < NS; i++)
            acc += g_pu[(size_t)(b*NS + i)*H + h] * fac[i];
        U[h] = acc;
    }
    __syncthreads();
    const float coef = 1.f / Ssum;   // Z cancels (non eps-corner); S > 0 always
    {
        const int v = tid;
        const float4* wr = (const float4*)(Wv + (size_t)v*H);
        const float4* Uv = (const float4*)U;
        float acc = 0.f;
        #pragma unroll 8
        for (int i = 0; i < H/4; i++) {
            float4 a = wr[i], xx = Uv[i];
            acc += a.x*xx.x + a.y*xx.y + a.z*xx.z + a.w*xx.w;
        }
        out[b*V + v] = acc * coef + bv[v] * (Ssum * coef);
    }
    if (tid == 0) { g_m[b] = m; g_coef[b] = coef; }
}

// ---------------- Kernel D: write attention output (vectorized) ----------------
__global__ void attn_out_kernel(const int* __restrict__ lens, float* __restrict__ out) {
    const int idx = blockIdx.x * 256 + threadIdx.x;  // < B*T/4
    const int base = idx * 4;
    const int b = base >> 11;        // T = 2048
    const int t = base & (T - 1);
    int len = lens[b];
    if (b == 0) len = T;
    if (len > T) len = T;
    const float4 e = ((const float4*)g_e)[idx];
    const float m = g_m[b], c = g_coef[b];
    float4 r;
    r.x = (t + 0 < len) ? __expf(e.x - m) * c : 0.f;
    r.y = (t + 1 < len) ? __expf(e.y - m) * c : 0.f;
    r.z = (t + 2 < len) ? __expf(e.z - m) * c : 0.f;
    r.w = (t + 3 < len) ? __expf(e.w - m) * c : 0.f;
    ((float4*)(out + B*V))[idx] = r;
}

extern "C" void kernel_launch(void* const* d_in, const int* in_sizes, int n_in,
                              void* d_out, int out_size) {
    const float* state = (const float*)d_in[0];
    const float* x     = (const float*)d_in[1];  // listener_output (B,T,H)
    const int*   lens  = (const int*)  d_in[2];
    const float* Ws    = (const float*)d_in[3];
    const float* bs    = (const float*)d_in[4];
    const float* Wh    = (const float*)d_in[5];
    const float* bh    = (const float*)d_in[6];
    const float* Wv    = (const float*)d_in[7];
    const float* bv    = (const float*)d_in[8];
    float* out = (float*)d_out;

    prep_kernel<<<B, 256>>>(state, Ws, bs, Wh, bh);
    dim3 grid(NS, B);
    flash_kernel<<<grid, 256>>>(x, lens);
    combine_kernel<<<B, 128>>>(Wv, bv, out);
    attn_out_kernel<<<(B*T/4)/256, 256>>>(lens, out);
}

// round 3
// speedup vs baseline: 1.5710x; 1.1153x over previous
#include <cuda_runtime.h>
#include <math.h>

#define B 64
#define T 2048
#define H 512
#define S 512
#define K 128
#define V 128
#define NS 32
#define CHUNK (T/NS)        // 64 rows per CTA
#define TILE 16             // rows per smem tile
#define FTHREADS 512

// ---- scratch (no device allocations allowed) ----
__device__ float g_q[B*K];        // query per batch
__device__ float g_c[B];          // q . bh
__device__ float g_w[B*H];        // folded query-key weight per batch
__device__ float g_e[B*T];        // energies (valid t only)
__device__ float g_pm[B*NS];      // partial max
__device__ float g_ps[B*NS];      // partial masked sum S
__device__ float g_pu[B*NS*H];    // partial weighted sums

__device__ __forceinline__ void cp16(float* smem, const float* gmem) {
    unsigned s = (unsigned)__cvta_generic_to_shared(smem);
    asm volatile("cp.async.cg.shared.global [%0], [%1], 16;" :: "r"(s), "l"(gmem));
}

// ---------------- Kernel A1: q_b = Ws state_b + bs ; c_b = q.bh ----------------
__global__ void prep_q_kernel(const float* __restrict__ state,
                              const float* __restrict__ Ws, const float* __restrict__ bs,
                              const float* __restrict__ bh) {
    const int b = blockIdx.x, tid = threadIdx.x;   // 128 threads, one k each
    __shared__ float st[S];
    __shared__ float prod[K];
    #pragma unroll
    for (int i = 0; i < S/128; i++) st[tid + i*128] = state[b*S + tid + i*128];
    __syncthreads();
    const float4* wr  = (const float4*)(Ws + (size_t)tid*S);
    const float4* stv = (const float4*)st;
    float acc = 0.f;
    #pragma unroll 8
    for (int i = 0; i < S/4; i++) {
        float4 a = wr[i], x = stv[i];
        acc += a.x*x.x + a.y*x.y + a.z*x.z + a.w*x.w;
    }
    const float q = acc + bs[tid];
    g_q[b*K + tid] = q;
    prod[tid] = q * bh[tid];
    __syncthreads();
    if (tid == 0) {
        float c = 0.f;
        #pragma unroll 8
        for (int k = 0; k < K; k++) c += prod[k];
        g_c[b] = c;
    }
}

// ---------------- Kernel A2: w_b = Wh^T q_b ----------------
__global__ void prep_w_kernel(const float* __restrict__ Wh) {
    const int half = blockIdx.x, b = blockIdx.y;   // 256 threads, one h each
    const int tid = threadIdx.x;
    const int h = half*256 + tid;
    __shared__ float qs[K];
    if (tid < K) qs[tid] = g_q[b*K + tid];
    __syncthreads();
    float acc = 0.f;
    #pragma unroll 8
    for (int k = 0; k < K; k++) acc += Wh[(size_t)k*H + h] * qs[k];
    g_w[b*H + h] = acc;
}

// ---------------- Kernel B: flash pass (valid rows only) ----------------
// grid (NS, B), 512 threads, dynamic smem double-buffered cp.async tiles.
__global__ void __launch_bounds__(FTHREADS) flash_kernel(const float* __restrict__ x,
                                                         const int* __restrict__ lens) {
    extern __shared__ float sm[];
    float* buf0 = sm;                    // TILE*H
    float* buf1 = sm + TILE*H;           // TILE*H
    float* wsm  = sm + 2*TILE*H;         // H
    float* esm  = wsm + H;               // TILE
    float* psm  = esm + TILE;            // TILE

    const int split = blockIdx.x, b = blockIdx.y;
    const int tid = threadIdx.x;
    const int warp = tid >> 5, lane = tid & 31;

    int len = lens[b];
    if (b == 0) len = T;
    if (len > T) len = T;
    const int t0 = split * CHUNK;
    int rows = len - t0;
    if (rows > CHUNK) rows = CHUNK;
    const int pi = b*NS + split;
    if (rows <= 0) {
        if (tid == 0) { g_pm[pi] = -INFINITY; g_ps[pi] = 0.f; }
        g_pu[(size_t)pi*H + tid] = 0.f;
        return;
    }
    const int ntiles = (rows + TILE - 1) / TILE;

    const float* xb = x + (size_t)b*T*H + (size_t)t0*H;

    // prefetch tile 0 (always full TILE rows; in-bounds, finite data)
    {
        #pragma unroll
        for (int i = 0; i < (TILE*H/4)/FTHREADS; i++)
            cp16(buf0 + (tid + i*FTHREADS)*4, xb + (size_t)(tid + i*FTHREADS)*4);
        asm volatile("cp.async.commit_group;");
    }

    wsm[tid] = g_w[b*H + tid];
    const float cb = g_c[b];

    float m = -INFINITY, Ssum = 0.f, u = 0.f;

    for (int ti = 0; ti < ntiles; ti++) {
        float* tl = (ti & 1) ? buf1 : buf0;
        if (ti + 1 < ntiles) {
            float* dst = (ti & 1) ? buf0 : buf1;
            const float* src = xb + (size_t)(ti+1)*TILE*H;
            #pragma unroll
            for (int i = 0; i < (TILE*H/4)/FTHREADS; i++)
                cp16(dst + (tid + i*FTHREADS)*4, src + (size_t)(tid + i*FTHREADS)*4);
            asm volatile("cp.async.commit_group;");
            asm volatile("cp.async.wait_group 1;");
        } else {
            asm volatile("cp.async.wait_group 0;");
        }
        __syncthreads();

        // energy: one warp per row (16 warps, 16 rows)
        {
            const int r = warp;
            const float4* row = (const float4*)(tl + r*H);
            const float4* wv  = (const float4*)wsm;
            float acc = 0.f;
            #pragma unroll
            for (int i = 0; i < H/128; i++) {
                float4 a = row[lane + i*32], w = wv[lane + i*32];
                acc += a.x*w.x + a.y*w.y + a.z*w.z + a.w*w.w;
            }
            #pragma unroll
            for (int o = 16; o > 0; o >>= 1)
                acc += __shfl_xor_sync(0xffffffffu, acc, o);
            if (lane == 0) {
                const int t = t0 + ti*TILE + r;
                const float e = acc + cb;
                if (t < len) { esm[r] = e; g_e[b*T + t] = e; }
                else         { esm[r] = -INFINITY; }
            }
        }
        __syncthreads();
        // online softmax update (replicated; identical across threads)
        float tmax = esm[0];
        #pragma unroll
        for (int r = 1; r < TILE; r++) tmax = fmaxf(tmax, esm[r]);
        const float m_new = fmaxf(m, tmax);
        const float scale = __expf(m - m_new);
        u *= scale; Ssum *= scale;
        m = m_new;
        if (tid < TILE) psm[tid] = __expf(esm[tid] - m_new);  // exp(-inf)=0
        __syncthreads();
        #pragma unroll
        for (int r = 0; r < TILE; r++) {
            const float p = psm[r];
            Ssum += p;
            u += p * tl[r*H + tid];
        }
        __syncthreads();  // buffer free before it is prefetched again
    }

    g_pu[(size_t)pi*H + tid] = u;
    if (tid == 0) { g_pm[pi] = m; g_ps[pi] = Ssum; }
}

// ---------------- Kernel C: combine partials + context GEMV + attention out ----------------
__global__ void combine_kernel(const float* __restrict__ Wv, const float* __restrict__ bv,
                               const int* __restrict__ lens, float* __restrict__ out) {
    const int b = blockIdx.x, tid = threadIdx.x;  // 256 threads
    __shared__ float U[H];
    __shared__ float fac[NS];
    float m = -INFINITY;
    #pragma unroll
    for (int i = 0; i < NS; i++) m = fmaxf(m, g_pm[b*NS + i]);
    if (tid < NS) fac[tid] = __expf(g_pm[b*NS + tid] - m);
    __syncthreads();
    float Ssum = 0.f;
    #pragma unroll
    for (int i = 0; i < NS; i++) Ssum += g_ps[b*NS + i] * fac[i];
    #pragma unroll
    for (int j = 0; j < H/256; j++) {
        const int h = tid + j*256;
        float acc = 0.f;
        #pragma unroll
        for (int i = 0; i < NS; i++)
            acc += g_pu[(size_t)(b*NS + i)*H + h] * fac[i];
        U[h] = acc;
    }
    __syncthreads();
    const float coef = 1.f / Ssum;   // Z cancels (non eps-corner); Ssum > 0 always
    if (tid < V) {
        const int v = tid;
        const float4* wr = (const float4*)(Wv + (size_t)v*H);
        const float4* Uv = (const float4*)U;
        float acc = 0.f;
        #pragma unroll 8
        for (int i = 0; i < H/4; i++) {
            float4 a = wr[i], xx = Uv[i];
            acc += a.x*xx.x + a.y*xx.y + a.z*xx.z + a.w*xx.w;
        }
        out[b*V + v] = acc * coef + bv[v] * (Ssum * coef);
    }
    // attention output for this batch
    int len = lens[b];
    if (b == 0) len = T;
    if (len > T) len = T;
    #pragma unroll
    for (int j = 0; j < T/4/256; j++) {
        const int i = tid + j*256;       // float4 index within row
        const int t = i * 4;
        const float4 e = ((const float4*)(g_e + b*T))[i];
        float4 r;
        r.x = (t + 0 < len) ? __expf(e.x - m) * coef : 0.f;
        r.y = (t + 1 < len) ? __expf(e.y - m) * coef : 0.f;
        r.z = (t + 2 < len) ? __expf(e.z - m) * coef : 0.f;
        r.w = (t + 3 < len) ? __expf(e.w - m) * coef : 0.f;
        ((float4*)(out + B*V + b*T))[i] = r;
    }
}

extern "C" void kernel_launch(void* const* d_in, const int* in_sizes, int n_in,
                              void* d_out, int out_size) {
    const float* state = (const float*)d_in[0];
    const float* x     = (const float*)d_in[1];  // listener_output (B,T,H)
    const int*   lens  = (const int*)  d_in[2];
    const float* Ws    = (const float*)d_in[3];
    const float* bs    = (const float*)d_in[4];
    const float* Wh    = (const float*)d_in[5];
    const float* bh    = (const float*)d_in[6];
    const float* Wv    = (const float*)d_in[7];
    const float* bv    = (const float*)d_in[8];
    float* out = (float*)d_out;

    const int smem_bytes = (2*TILE*H + H + 2*TILE) * (int)sizeof(float);  // ~66 KB
    cudaFuncSetAttribute(flash_kernel, cudaFuncAttributeMaxDynamicSharedMemorySize, smem_bytes);

    prep_q_kernel<<<B, 128>>>(state, Ws, bs, bh);
    dim3 gw(2, B);
    prep_w_kernel<<<gw, 256>>>(Wh);
    dim3 grid(NS, B);
    flash_kernel<<<grid, FTHREADS, smem_bytes>>>(x, lens);
    combine_kernel<<<B, 256>>>(Wv, bv, lens, out);
}